// round 4
// baseline (speedup 1.0000x reference)
#include <cuda_runtime.h>
#include <cstdint>

#define N_NODES 50000
#define N_EDGES 800000
#define DIM     128
#define LAYERS  5

#define SCAN_CHUNK  256
#define SCAN_BLOCKS ((N_NODES + SCAN_CHUNK - 1) / SCAN_CHUNK)   // 196

// fused-kernel smem layout (floats)
#define AS_PAD   129                  // k-major A tile: As[k][row], row-dim padded
#define AS_ELEMS (DIM * AS_PAD)       // 128*129 = 16512
#define BS_ELEMS (16 * DIM)           // 2048
#define SMEM_BYTES ((AS_ELEMS + BS_ELEMS) * 4)   // 74240

// ---------------- scratch (no allocation allowed) ----------------
__device__ float g_h[2][N_NODES * DIM];   // ping-pong hidden buffers
__device__ int   g_deg_out[N_NODES];
__device__ int   g_deg_in[N_NODES];
__device__ float g_norm_src[N_NODES];
__device__ float g_norm_dst[N_NODES];
__device__ int   g_row_ptr[N_NODES + 1];
__device__ int   g_cursor[N_NODES];
__device__ int   g_csr_src[N_EDGES];
__device__ float g_csr_w[N_EDGES];
__device__ int   g_partial[SCAN_BLOCKS];

// ---------------- degree / norm computation ----------------
__global__ void zero_deg_kernel() {
    int i = blockIdx.x * blockDim.x + threadIdx.x;
    if (i < N_NODES) { g_deg_out[i] = 0; g_deg_in[i] = 0; }
}

__global__ void count_deg_kernel(const int* __restrict__ src,
                                 const int* __restrict__ dst) {
    int e = blockIdx.x * blockDim.x + threadIdx.x;
    if (e < N_EDGES) {
        atomicAdd(&g_deg_out[src[e]], 1);
        atomicAdd(&g_deg_in[dst[e]], 1);
    }
}

__global__ void finalize_norm_kernel() {
    int i = blockIdx.x * blockDim.x + threadIdx.x;
    if (i < N_NODES) {
        g_norm_src[i] = rsqrtf(fmaxf((float)g_deg_out[i], 1.0f));
        g_norm_dst[i] = rsqrtf(fmaxf((float)g_deg_in[i], 1.0f));
    }
}

// ---------------- decoupled scan: phase A (per-block sums) ----------------
__global__ __launch_bounds__(SCAN_CHUNK)
void scan_partial_kernel() {
    __shared__ int wsum[SCAN_CHUNK / 32];
    int tid  = threadIdx.x;
    int lane = tid & 31;
    int wid  = tid >> 5;
    int i = blockIdx.x * SCAN_CHUNK + tid;
    int v = (i < N_NODES) ? g_deg_in[i] : 0;
    #pragma unroll
    for (int o = 16; o > 0; o >>= 1) v += __shfl_down_sync(0xFFFFFFFFu, v, o);
    if (lane == 0) wsum[wid] = v;
    __syncthreads();
    if (tid == 0) {
        int s = 0;
        #pragma unroll
        for (int w = 0; w < SCAN_CHUNK / 32; w++) s += wsum[w];
        g_partial[blockIdx.x] = s;
    }
}

// ---------------- phase B (1 block: exclusive scan of partials) ----------------
__global__ __launch_bounds__(256)
void scan_offsets_kernel() {
    __shared__ int wsum[8];
    int tid  = threadIdx.x;
    int lane = tid & 31;
    int wid  = tid >> 5;
    int v = (tid < SCAN_BLOCKS) ? g_partial[tid] : 0;
    int orig = v;
    #pragma unroll
    for (int o = 1; o < 32; o <<= 1) {
        int n = __shfl_up_sync(0xFFFFFFFFu, v, o);
        if (lane >= o) v += n;
    }
    if (lane == 31) wsum[wid] = v;
    __syncthreads();
    if (wid == 0 && lane < 8) {
        int s = wsum[lane];
        #pragma unroll
        for (int o = 1; o < 8; o <<= 1) {
            int n = __shfl_up_sync(0xFFu, s, o);
            if (lane >= o) s += n;
        }
        wsum[lane] = s;
    }
    __syncthreads();
    int excl = v - orig + (wid > 0 ? wsum[wid - 1] : 0);
    if (tid < SCAN_BLOCKS) g_partial[tid] = excl;
}

// ---------------- phase C (per-block scan + write row_ptr / cursor) ----------------
__global__ __launch_bounds__(SCAN_CHUNK)
void scan_write_kernel() {
    __shared__ int wsum[SCAN_CHUNK / 32];
    int tid  = threadIdx.x;
    int lane = tid & 31;
    int wid  = tid >> 5;
    int i = blockIdx.x * SCAN_CHUNK + tid;
    int orig = (i < N_NODES) ? g_deg_in[i] : 0;
    int v = orig;
    #pragma unroll
    for (int o = 1; o < 32; o <<= 1) {
        int n = __shfl_up_sync(0xFFFFFFFFu, v, o);
        if (lane >= o) v += n;
    }
    if (lane == 31) wsum[wid] = v;
    __syncthreads();
    if (wid == 0 && lane < SCAN_CHUNK / 32) {
        int s = wsum[lane];
        #pragma unroll
        for (int o = 1; o < SCAN_CHUNK / 32; o <<= 1) {
            int n = __shfl_up_sync(0xFFu, s, o);
            if (lane >= o) s += n;
        }
        wsum[lane] = s;
    }
    __syncthreads();
    int excl = v - orig + (wid > 0 ? wsum[wid - 1] : 0) + g_partial[blockIdx.x];
    if (i < N_NODES) {
        g_row_ptr[i] = excl;
        g_cursor[i]  = excl;
        if (i == N_NODES - 1) g_row_ptr[N_NODES] = excl + orig;  // == N_EDGES
    }
}

// ---------------- scatter edges into CSR with fused edge weight ----------------
__global__ void scatter_edges_kernel(const int* __restrict__ src,
                                     const int* __restrict__ dst) {
    int e = blockIdx.x * blockDim.x + threadIdx.x;
    if (e < N_EDGES) {
        int s = src[e];
        int d = dst[e];
        int pos = atomicAdd(&g_cursor[d], 1);
        g_csr_src[pos] = s;
        g_csr_w[pos]   = g_norm_src[s] * g_norm_dst[d];
    }
}

// ---------------- fused layer: SpMM (gather into smem) + GEMM + bias + relu ----
// Block = 128 node rows, 256 threads.
// Phase 1: warp-per-node CSR gather, accumulate in regs, write k-major As.
// Phase 2: register-tiled GEMM out = relu(As @ W + b), A from smem.
__global__ __launch_bounds__(256, 2)
void fused_layer_kernel(const float* __restrict__ feat,
                        const float* __restrict__ Wl,
                        const float* __restrict__ bl,
                        float* __restrict__ ext_out,
                        int in_sel, int out_sel) {
    extern __shared__ float smem[];
    float* As = smem;                 // [DIM][AS_PAD]  k-major
    float* Bs = smem + AS_ELEMS;      // [16][DIM]      k-major chunk of W

    const float* __restrict__ h = (in_sel < 0) ? feat : g_h[in_sel];
    float* __restrict__ out = (out_sel < 0) ? ext_out : g_h[out_sel];

    const int tid  = threadIdx.x;
    const int lane = tid & 31;
    const int wrp  = tid >> 5;          // 0..7
    const int rowBase = blockIdx.x * 128;

    // ---------------- phase 1: SpMM into As ----------------
    #pragma unroll 1
    for (int n = 0; n < 16; n++) {
        int localRow = n * 8 + wrp;
        int node = rowBase + localRow;

        float4 s0 = make_float4(0.f, 0.f, 0.f, 0.f);
        float4 s1 = make_float4(0.f, 0.f, 0.f, 0.f);
        float4 s2 = make_float4(0.f, 0.f, 0.f, 0.f);
        float4 s3 = make_float4(0.f, 0.f, 0.f, 0.f);

        if (node < N_NODES) {
            int beg = g_row_ptr[node];
            int end = g_row_ptr[node + 1];
            int i = beg;
            for (; i + 3 < end; i += 4) {
                int   e0 = g_csr_src[i];
                int   e1 = g_csr_src[i + 1];
                int   e2 = g_csr_src[i + 2];
                int   e3 = g_csr_src[i + 3];
                float w0 = g_csr_w[i];
                float w1 = g_csr_w[i + 1];
                float w2 = g_csr_w[i + 2];
                float w3 = g_csr_w[i + 3];
                float4 v0 = ((const float4*)(h + (size_t)e0 * DIM))[lane];
                float4 v1 = ((const float4*)(h + (size_t)e1 * DIM))[lane];
                float4 v2 = ((const float4*)(h + (size_t)e2 * DIM))[lane];
                float4 v3 = ((const float4*)(h + (size_t)e3 * DIM))[lane];
                s0.x += v0.x * w0; s0.y += v0.y * w0; s0.z += v0.z * w0; s0.w += v0.w * w0;
                s1.x += v1.x * w1; s1.y += v1.y * w1; s1.z += v1.z * w1; s1.w += v1.w * w1;
                s2.x += v2.x * w2; s2.y += v2.y * w2; s2.z += v2.z * w2; s2.w += v2.w * w2;
                s3.x += v3.x * w3; s3.y += v3.y * w3; s3.z += v3.z * w3; s3.w += v3.w * w3;
            }
            for (; i < end; i++) {
                int   e0 = g_csr_src[i];
                float w0 = g_csr_w[i];
                float4 v0 = ((const float4*)(h + (size_t)e0 * DIM))[lane];
                s0.x += v0.x * w0; s0.y += v0.y * w0; s0.z += v0.z * w0; s0.w += v0.w * w0;
            }
        }
        float4 s;
        s.x = (s0.x + s1.x) + (s2.x + s3.x);
        s.y = (s0.y + s1.y) + (s2.y + s3.y);
        s.z = (s0.z + s1.z) + (s2.z + s3.z);
        s.w = (s0.w + s1.w) + (s2.w + s3.w);

        // write k-major: As[k][localRow], lane covers k = lane*4 .. lane*4+3
        int kbase = lane * 4;
        As[(kbase + 0) * AS_PAD + localRow] = s.x;
        As[(kbase + 1) * AS_PAD + localRow] = s.y;
        As[(kbase + 2) * AS_PAD + localRow] = s.z;
        As[(kbase + 3) * AS_PAD + localRow] = s.w;
    }

    // ---------------- phase 2: GEMM + bias + relu ----------------
    const int tx = tid & 15;
    const int ty = tid >> 4;

    float acc[8][8];
    #pragma unroll
    for (int i = 0; i < 8; i++)
        #pragma unroll
        for (int j = 0; j < 8; j++) acc[i][j] = 0.0f;

    for (int kb = 0; kb < DIM; kb += 16) {
        __syncthreads();   // protect Bs overwrite; first iter also orders As
        // load B chunk [16][128], coalesced float4
        #pragma unroll
        for (int it = 0; it < 2; it++) {
            int f = tid + it * 256;
            int kr = f >> 5;
            int c  = (f & 31) * 4;
            *(float4*)&Bs[kr * DIM + c] =
                *(const float4*)(&Wl[(size_t)(kb + kr) * DIM + c]);
        }
        __syncthreads();

        #pragma unroll
        for (int kk = 0; kk < 16; kk++) {
            float a[8], bv[8];
            #pragma unroll
            for (int i = 0; i < 8; i++) a[i] = As[(kb + kk) * AS_PAD + ty * 8 + i];
            #pragma unroll
            for (int j = 0; j < 8; j++) bv[j] = Bs[kk * DIM + tx * 8 + j];
            #pragma unroll
            for (int i = 0; i < 8; i++)
                #pragma unroll
                for (int j = 0; j < 8; j++)
                    acc[i][j] += a[i] * bv[j];
        }
    }

    float bias[8];
    #pragma unroll
    for (int j = 0; j < 8; j++) bias[j] = bl[tx * 8 + j];

    #pragma unroll
    for (int i = 0; i < 8; i++) {
        int grow = rowBase + ty * 8 + i;
        if (grow < N_NODES) {
            float4 o0, o1;
            o0.x = fmaxf(acc[i][0] + bias[0], 0.f);
            o0.y = fmaxf(acc[i][1] + bias[1], 0.f);
            o0.z = fmaxf(acc[i][2] + bias[2], 0.f);
            o0.w = fmaxf(acc[i][3] + bias[3], 0.f);
            o1.x = fmaxf(acc[i][4] + bias[4], 0.f);
            o1.y = fmaxf(acc[i][5] + bias[5], 0.f);
            o1.z = fmaxf(acc[i][6] + bias[6], 0.f);
            o1.w = fmaxf(acc[i][7] + bias[7], 0.f);
            float* orow = out + (size_t)grow * DIM + tx * 8;
            *(float4*)(orow)     = o0;
            *(float4*)(orow + 4) = o1;
        }
    }
}

// ---------------- launch ----------------
extern "C" void kernel_launch(void* const* d_in, const int* in_sizes, int n_in,
                              void* d_out, int out_size) {
    const float* feat = (const float*)d_in[0];   // [N, D]
    const int*   src  = (const int*)d_in[1];     // [E]
    const int*   dst  = (const int*)d_in[2];     // [E]
    const float* W    = (const float*)d_in[3];   // [L, D, D]
    const float* b    = (const float*)d_in[4];   // [L, D]
    float* out = (float*)d_out;                  // [N, D]

    (void)in_sizes; (void)n_in; (void)out_size;

    // raise dynamic smem cap (idempotent, not an allocation)
    cudaFuncSetAttribute(fused_layer_kernel,
                         cudaFuncAttributeMaxDynamicSharedMemorySize, SMEM_BYTES);

    // ---- one-time CSR build (per launch, graph-capturable) ----
    zero_deg_kernel<<<(N_NODES + 255) / 256, 256>>>();
    count_deg_kernel<<<(N_EDGES + 255) / 256, 256>>>(src, dst);
    finalize_norm_kernel<<<(N_NODES + 255) / 256, 256>>>();
    scan_partial_kernel<<<SCAN_BLOCKS, SCAN_CHUNK>>>();
    scan_offsets_kernel<<<1, 256>>>();
    scan_write_kernel<<<SCAN_BLOCKS, SCAN_CHUNK>>>();
    scatter_edges_kernel<<<(N_EDGES + 255) / 256, 256>>>(src, dst);

    const int blocks = (N_NODES + 127) / 128;    // 391

    for (int l = 0; l < LAYERS; l++) {
        int in_sel  = (l == 0) ? -1 : ((l - 1) & 1);
        int out_sel = (l == LAYERS - 1) ? -1 : (l & 1);

        fused_layer_kernel<<<blocks, 256, SMEM_BYTES>>>(
            feat, W + (size_t)l * DIM * DIM, b + (size_t)l * DIM,
            out, in_sel, out_sel);
    }
}

// round 5
// speedup vs baseline: 1.3417x; 1.3417x over previous
#include <cuda_runtime.h>
#include <cstdint>

#define N_NODES 50000
#define N_EDGES 800000
#define DIM     128
#define LAYERS  5

#define SCAN_CHUNK  256
#define SCAN_BLOCKS ((N_NODES + SCAN_CHUNK - 1) / SCAN_CHUNK)   // 196

// ---------------- scratch (no allocation allowed) ----------------
__device__ float g_h[2][N_NODES * DIM];   // ping-pong hidden buffers
__device__ float g_agg[N_NODES * DIM];    // aggregation buffer
__device__ int   g_deg_out[N_NODES];
__device__ int   g_deg_in[N_NODES];
__device__ float g_norm_src[N_NODES];
__device__ int   g_row_ptr[N_NODES + 1];
__device__ int   g_cursor[N_NODES];
__device__ int2  g_csr[N_EDGES];          // .x = src node, .y = weight bits
__device__ int   g_partial[SCAN_BLOCKS];

// ---------------- degree / norm computation ----------------
__global__ void zero_deg_kernel() {
    int i = blockIdx.x * blockDim.x + threadIdx.x;
    if (i < N_NODES) { g_deg_out[i] = 0; g_deg_in[i] = 0; }
}

__global__ void count_deg_kernel(const int* __restrict__ src,
                                 const int* __restrict__ dst) {
    int e = blockIdx.x * blockDim.x + threadIdx.x;
    if (e < N_EDGES) {
        atomicAdd(&g_deg_out[src[e]], 1);
        atomicAdd(&g_deg_in[dst[e]], 1);
    }
}

// ---------------- decoupled scan: phase A (per-block sums) ----------------
__global__ __launch_bounds__(SCAN_CHUNK)
void scan_partial_kernel() {
    __shared__ int wsum[SCAN_CHUNK / 32];
    int tid  = threadIdx.x;
    int lane = tid & 31;
    int wid  = tid >> 5;
    int i = blockIdx.x * SCAN_CHUNK + tid;
    int v = (i < N_NODES) ? g_deg_in[i] : 0;
    #pragma unroll
    for (int o = 16; o > 0; o >>= 1) v += __shfl_down_sync(0xFFFFFFFFu, v, o);
    if (lane == 0) wsum[wid] = v;
    __syncthreads();
    if (tid == 0) {
        int s = 0;
        #pragma unroll
        for (int w = 0; w < SCAN_CHUNK / 32; w++) s += wsum[w];
        g_partial[blockIdx.x] = s;
    }
}

// ---------------- phase B (1 block: exclusive scan of partials) ----------------
__global__ __launch_bounds__(256)
void scan_offsets_kernel() {
    __shared__ int wsum[8];
    int tid  = threadIdx.x;
    int lane = tid & 31;
    int wid  = tid >> 5;
    int v = (tid < SCAN_BLOCKS) ? g_partial[tid] : 0;
    int orig = v;
    #pragma unroll
    for (int o = 1; o < 32; o <<= 1) {
        int n = __shfl_up_sync(0xFFFFFFFFu, v, o);
        if (lane >= o) v += n;
    }
    if (lane == 31) wsum[wid] = v;
    __syncthreads();
    if (wid == 0 && lane < 8) {
        int s = wsum[lane];
        #pragma unroll
        for (int o = 1; o < 8; o <<= 1) {
            int n = __shfl_up_sync(0xFFu, s, o);
            if (lane >= o) s += n;
        }
        wsum[lane] = s;
    }
    __syncthreads();
    int excl = v - orig + (wid > 0 ? wsum[wid - 1] : 0);
    if (tid < SCAN_BLOCKS) g_partial[tid] = excl;
}

// ---------------- phase C (per-block scan + row_ptr/cursor/norms) --------------
__global__ __launch_bounds__(SCAN_CHUNK)
void scan_write_kernel() {
    __shared__ int wsum[SCAN_CHUNK / 32];
    int tid  = threadIdx.x;
    int lane = tid & 31;
    int wid  = tid >> 5;
    int i = blockIdx.x * SCAN_CHUNK + tid;
    int orig = (i < N_NODES) ? g_deg_in[i] : 0;
    int v = orig;
    #pragma unroll
    for (int o = 1; o < 32; o <<= 1) {
        int n = __shfl_up_sync(0xFFFFFFFFu, v, o);
        if (lane >= o) v += n;
    }
    if (lane == 31) wsum[wid] = v;
    __syncthreads();
    if (wid == 0 && lane < SCAN_CHUNK / 32) {
        int s = wsum[lane];
        #pragma unroll
        for (int o = 1; o < SCAN_CHUNK / 32; o <<= 1) {
            int n = __shfl_up_sync(0xFFu, s, o);
            if (lane >= o) s += n;
        }
        wsum[lane] = s;
    }
    __syncthreads();
    int excl = v - orig + (wid > 0 ? wsum[wid - 1] : 0) + g_partial[blockIdx.x];
    if (i < N_NODES) {
        g_row_ptr[i] = excl;
        g_cursor[i]  = excl;
        if (i == N_NODES - 1) g_row_ptr[N_NODES] = excl + orig;  // == N_EDGES
        // fold norm computation here (one less kernel)
        g_norm_src[i] = rsqrtf(fmaxf((float)g_deg_out[i], 1.0f));
        // store dst norm in g_deg_in slot? keep separate: reuse deg_in as float
    }
}

// norm_dst computed on the fly in scatter from deg_in (int -> rsqrt)

// ---------------- scatter edges into packed CSR with fused edge weight --------
__global__ void scatter_edges_kernel(const int* __restrict__ src,
                                     const int* __restrict__ dst) {
    int e = blockIdx.x * blockDim.x + threadIdx.x;
    if (e < N_EDGES) {
        int s = src[e];
        int d = dst[e];
        int pos = atomicAdd(&g_cursor[d], 1);
        float nd = rsqrtf(fmaxf((float)g_deg_in[d], 1.0f));
        float w  = g_norm_src[s] * nd;
        g_csr[pos] = make_int2(s, __float_as_int(w));
    }
}

// ---------------- SpMM (CSR gather): one warp per dst node ----------------
// agg[d] = sum_{edges into d} w[e] * h[src[e]]   (norms pre-folded into w)
__global__ __launch_bounds__(256)
void spmm_csr_kernel(const float* __restrict__ feat, int in_sel) {
    int node = blockIdx.x * (blockDim.x >> 5) + (threadIdx.x >> 5);
    if (node >= N_NODES) return;
    int lane = threadIdx.x & 31;

    const float* __restrict__ h = (in_sel < 0) ? feat : g_h[in_sel];
    const int2* __restrict__ csr = g_csr;

    int beg = g_row_ptr[node];
    int end = g_row_ptr[node + 1];

    float4 s0 = make_float4(0.f, 0.f, 0.f, 0.f);
    float4 s1 = make_float4(0.f, 0.f, 0.f, 0.f);
    float4 s2 = make_float4(0.f, 0.f, 0.f, 0.f);
    float4 s3 = make_float4(0.f, 0.f, 0.f, 0.f);

    int i = beg;
    for (; i + 3 < end; i += 4) {
        int2 e0 = csr[i];
        int2 e1 = csr[i + 1];
        int2 e2 = csr[i + 2];
        int2 e3 = csr[i + 3];
        float4 v0 = ((const float4*)(h + (size_t)e0.x * DIM))[lane];
        float4 v1 = ((const float4*)(h + (size_t)e1.x * DIM))[lane];
        float4 v2 = ((const float4*)(h + (size_t)e2.x * DIM))[lane];
        float4 v3 = ((const float4*)(h + (size_t)e3.x * DIM))[lane];
        float w0 = __int_as_float(e0.y);
        float w1 = __int_as_float(e1.y);
        float w2 = __int_as_float(e2.y);
        float w3 = __int_as_float(e3.y);
        s0.x += v0.x * w0; s0.y += v0.y * w0; s0.z += v0.z * w0; s0.w += v0.w * w0;
        s1.x += v1.x * w1; s1.y += v1.y * w1; s1.z += v1.z * w1; s1.w += v1.w * w1;
        s2.x += v2.x * w2; s2.y += v2.y * w2; s2.z += v2.z * w2; s2.w += v2.w * w2;
        s3.x += v3.x * w3; s3.y += v3.y * w3; s3.z += v3.z * w3; s3.w += v3.w * w3;
    }
    for (; i < end; i++) {
        int2 e0 = csr[i];
        float w0 = __int_as_float(e0.y);
        float4 v0 = ((const float4*)(h + (size_t)e0.x * DIM))[lane];
        s0.x += v0.x * w0; s0.y += v0.y * w0; s0.z += v0.z * w0; s0.w += v0.w * w0;
    }

    float4 o;
    o.x = (s0.x + s1.x) + (s2.x + s3.x);
    o.y = (s0.y + s1.y) + (s2.y + s3.y);
    o.z = (s0.z + s1.z) + (s2.z + s3.z);
    o.w = (s0.w + s1.w) + (s2.w + s3.w);
    ((float4*)(g_agg + (size_t)node * DIM))[lane] = o;
}

// ---------------- GEMM: out = relu(agg @ W + b) ----------------
// Tile: BM=128, BN=128, BK=16. 256 threads, 8x8 outputs per thread.
__global__ __launch_bounds__(256, 2)
void gemm_relu_kernel(const float* __restrict__ Wl,
                      const float* __restrict__ bl,
                      float* __restrict__ ext_out,
                      int out_sel) {
    float* __restrict__ out = (out_sel < 0) ? ext_out : g_h[out_sel];

    __shared__ float As[16][128];   // k-major A tile (transposed on store)
    __shared__ float Bs[16][128];   // k-major W tile

    const int tid = threadIdx.x;
    const int tx = tid & 15;
    const int ty = tid >> 4;
    const int rowBase = blockIdx.x * 128;

    float acc[8][8];
    #pragma unroll
    for (int i = 0; i < 8; i++)
        #pragma unroll
        for (int j = 0; j < 8; j++) acc[i][j] = 0.0f;

    for (int kb = 0; kb < DIM; kb += 16) {
        #pragma unroll
        for (int it = 0; it < 2; it++) {
            int f = tid + it * 256;          // float4 index, 0..511
            int r  = f >> 2;
            int c4 = f & 3;
            int grow = rowBase + r;
            float4 v = make_float4(0.f, 0.f, 0.f, 0.f);
            if (grow < N_NODES)
                v = *(const float4*)(&g_agg[(size_t)grow * DIM + kb + c4 * 4]);
            As[c4 * 4 + 0][r] = v.x;
            As[c4 * 4 + 1][r] = v.y;
            As[c4 * 4 + 2][r] = v.z;
            As[c4 * 4 + 3][r] = v.w;

            int kr = f >> 5;
            int c  = (f & 31) * 4;
            *(float4*)&Bs[kr][c] =
                *(const float4*)(&Wl[(size_t)(kb + kr) * DIM + c]);
        }
        __syncthreads();

        #pragma unroll
        for (int kk = 0; kk < 16; kk++) {
            float a[8], bv[8];
            #pragma unroll
            for (int i = 0; i < 8; i++) a[i] = As[kk][ty * 8 + i];
            #pragma unroll
            for (int j = 0; j < 8; j++) bv[j] = Bs[kk][tx * 8 + j];
            #pragma unroll
            for (int i = 0; i < 8; i++)
                #pragma unroll
                for (int j = 0; j < 8; j++)
                    acc[i][j] += a[i] * bv[j];
        }
        __syncthreads();
    }

    float bias[8];
    #pragma unroll
    for (int j = 0; j < 8; j++) bias[j] = bl[tx * 8 + j];

    #pragma unroll
    for (int i = 0; i < 8; i++) {
        int grow = rowBase + ty * 8 + i;
        if (grow < N_NODES) {
            float4 o0, o1;
            o0.x = fmaxf(acc[i][0] + bias[0], 0.f);
            o0.y = fmaxf(acc[i][1] + bias[1], 0.f);
            o0.z = fmaxf(acc[i][2] + bias[2], 0.f);
            o0.w = fmaxf(acc[i][3] + bias[3], 0.f);
            o1.x = fmaxf(acc[i][4] + bias[4], 0.f);
            o1.y = fmaxf(acc[i][5] + bias[5], 0.f);
            o1.z = fmaxf(acc[i][6] + bias[6], 0.f);
            o1.w = fmaxf(acc[i][7] + bias[7], 0.f);
            float* orow = out + (size_t)grow * DIM + tx * 8;
            *(float4*)(orow)     = o0;
            *(float4*)(orow + 4) = o1;
        }
    }
}

// ---------------- launch ----------------
extern "C" void kernel_launch(void* const* d_in, const int* in_sizes, int n_in,
                              void* d_out, int out_size) {
    const float* feat = (const float*)d_in[0];   // [N, D]
    const int*   src  = (const int*)d_in[1];     // [E]
    const int*   dst  = (const int*)d_in[2];     // [E]
    const float* W    = (const float*)d_in[3];   // [L, D, D]
    const float* b    = (const float*)d_in[4];   // [L, D]
    float* out = (float*)d_out;                  // [N, D]

    (void)in_sizes; (void)n_in; (void)out_size;

    // ---- one-time CSR build (per launch, graph-capturable) ----
    zero_deg_kernel<<<(N_NODES + 255) / 256, 256>>>();
    count_deg_kernel<<<(N_EDGES + 255) / 256, 256>>>(src, dst);
    scan_partial_kernel<<<SCAN_BLOCKS, SCAN_CHUNK>>>();
    scan_offsets_kernel<<<1, 256>>>();
    scan_write_kernel<<<SCAN_BLOCKS, SCAN_CHUNK>>>();
    scatter_edges_kernel<<<(N_EDGES + 255) / 256, 256>>>(src, dst);

    const int warps_per_block = 256 / 32;
    const int spmm_blocks = (N_NODES + warps_per_block - 1) / warps_per_block;
    const int gemm_blocks = (N_NODES + 127) / 128;

    for (int l = 0; l < LAYERS; l++) {
        int in_sel  = (l == 0) ? -1 : ((l - 1) & 1);
        int out_sel = (l == LAYERS - 1) ? -1 : (l & 1);

        spmm_csr_kernel<<<spmm_blocks, 256>>>(feat, in_sel);
        gemm_relu_kernel<<<gemm_blocks, 256>>>(
            W + (size_t)l * DIM * DIM, b + (size_t)l * DIM, out, out_sel);
    }
}

// round 6
// speedup vs baseline: 1.5698x; 1.1700x over previous
#include <cuda_runtime.h>
#include <cstdint>

#define N_NODES 50000
#define N_EDGES 800000
#define DIM     128
#define LAYERS  5

#define SCAN_CHUNK  256
#define SCAN_BLOCKS ((N_NODES + SCAN_CHUNK - 1) / SCAN_CHUNK)   // 196

// ---------------- scratch (no allocation allowed) ----------------
__device__ float g_h[2][N_NODES * DIM];   // ping-pong hidden buffers
__device__ float g_agg[N_NODES * DIM];    // aggregation buffer
__device__ int   g_deg_out[N_NODES];
__device__ int   g_deg_in[N_NODES];
__device__ float g_norm_src[N_NODES];
__device__ int   g_row_ptr[N_NODES + 1];
__device__ int   g_cursor[N_NODES];
__device__ int2  g_csr[N_EDGES];          // .x = src node, .y = weight bits
__device__ int   g_partial[SCAN_BLOCKS];
__device__ float g_Whi[LAYERS * DIM * DIM];
__device__ float g_Wlo[LAYERS * DIM * DIM];

// ---------------- tf32 helpers ----------------
__device__ __forceinline__ void split_tf32(float x, uint32_t& hi, uint32_t& lo) {
    uint32_t h;
    asm("cvt.rna.tf32.f32 %0, %1;" : "=r"(h) : "f"(x));
    float r = x - __uint_as_float(h);
    uint32_t l;
    asm("cvt.rna.tf32.f32 %0, %1;" : "=r"(l) : "f"(r));
    hi = h; lo = l;
}

__device__ __forceinline__ void mma_tf32(float c[4], const uint32_t a[4],
                                         uint32_t b0, uint32_t b1) {
    asm volatile(
        "mma.sync.aligned.m16n8k8.row.col.f32.tf32.tf32.f32 "
        "{%0,%1,%2,%3}, {%4,%5,%6,%7}, {%8,%9}, {%0,%1,%2,%3};"
        : "+f"(c[0]), "+f"(c[1]), "+f"(c[2]), "+f"(c[3])
        : "r"(a[0]), "r"(a[1]), "r"(a[2]), "r"(a[3]), "r"(b0), "r"(b1));
}

// ---------------- W split (once, all layers) ----------------
__global__ void split_w_kernel(const float* __restrict__ W) {
    int i = blockIdx.x * blockDim.x + threadIdx.x;
    if (i < LAYERS * DIM * DIM) {
        float w = W[i];
        uint32_t hb, lb;
        split_tf32(w, hb, lb);
        g_Whi[i] = __uint_as_float(hb);
        g_Wlo[i] = __uint_as_float(lb);
    }
}

// ---------------- degree computation ----------------
__global__ void zero_deg_kernel() {
    int i = blockIdx.x * blockDim.x + threadIdx.x;
    if (i < N_NODES) { g_deg_out[i] = 0; g_deg_in[i] = 0; }
}

__global__ void count_deg_kernel(const int* __restrict__ src,
                                 const int* __restrict__ dst) {
    int e = blockIdx.x * blockDim.x + threadIdx.x;
    if (e < N_EDGES) {
        atomicAdd(&g_deg_out[src[e]], 1);
        atomicAdd(&g_deg_in[dst[e]], 1);
    }
}

// ---------------- decoupled scan: phase A (per-block sums) ----------------
__global__ __launch_bounds__(SCAN_CHUNK)
void scan_partial_kernel() {
    __shared__ int wsum[SCAN_CHUNK / 32];
    int tid  = threadIdx.x;
    int lane = tid & 31;
    int wid  = tid >> 5;
    int i = blockIdx.x * SCAN_CHUNK + tid;
    int v = (i < N_NODES) ? g_deg_in[i] : 0;
    #pragma unroll
    for (int o = 16; o > 0; o >>= 1) v += __shfl_down_sync(0xFFFFFFFFu, v, o);
    if (lane == 0) wsum[wid] = v;
    __syncthreads();
    if (tid == 0) {
        int s = 0;
        #pragma unroll
        for (int w = 0; w < SCAN_CHUNK / 32; w++) s += wsum[w];
        g_partial[blockIdx.x] = s;
    }
}

// ---------------- phase B (1 block: exclusive scan of partials) ----------------
__global__ __launch_bounds__(256)
void scan_offsets_kernel() {
    __shared__ int wsum[8];
    int tid  = threadIdx.x;
    int lane = tid & 31;
    int wid  = tid >> 5;
    int v = (tid < SCAN_BLOCKS) ? g_partial[tid] : 0;
    int orig = v;
    #pragma unroll
    for (int o = 1; o < 32; o <<= 1) {
        int n = __shfl_up_sync(0xFFFFFFFFu, v, o);
        if (lane >= o) v += n;
    }
    if (lane == 31) wsum[wid] = v;
    __syncthreads();
    if (wid == 0 && lane < 8) {
        int s = wsum[lane];
        #pragma unroll
        for (int o = 1; o < 8; o <<= 1) {
            int n = __shfl_up_sync(0xFFu, s, o);
            if (lane >= o) s += n;
        }
        wsum[lane] = s;
    }
    __syncthreads();
    int excl = v - orig + (wid > 0 ? wsum[wid - 1] : 0);
    if (tid < SCAN_BLOCKS) g_partial[tid] = excl;
}

// ---------------- phase C (per-block scan + row_ptr/cursor/norms) --------------
__global__ __launch_bounds__(SCAN_CHUNK)
void scan_write_kernel() {
    __shared__ int wsum[SCAN_CHUNK / 32];
    int tid  = threadIdx.x;
    int lane = tid & 31;
    int wid  = tid >> 5;
    int i = blockIdx.x * SCAN_CHUNK + tid;
    int orig = (i < N_NODES) ? g_deg_in[i] : 0;
    int v = orig;
    #pragma unroll
    for (int o = 1; o < 32; o <<= 1) {
        int n = __shfl_up_sync(0xFFFFFFFFu, v, o);
        if (lane >= o) v += n;
    }
    if (lane == 31) wsum[wid] = v;
    __syncthreads();
    if (wid == 0 && lane < SCAN_CHUNK / 32) {
        int s = wsum[lane];
        #pragma unroll
        for (int o = 1; o < SCAN_CHUNK / 32; o <<= 1) {
            int n = __shfl_up_sync(0xFFu, s, o);
            if (lane >= o) s += n;
        }
        wsum[lane] = s;
    }
    __syncthreads();
    int excl = v - orig + (wid > 0 ? wsum[wid - 1] : 0) + g_partial[blockIdx.x];
    if (i < N_NODES) {
        g_row_ptr[i] = excl;
        g_cursor[i]  = excl;
        if (i == N_NODES - 1) g_row_ptr[N_NODES] = excl + orig;  // == N_EDGES
        g_norm_src[i] = rsqrtf(fmaxf((float)g_deg_out[i], 1.0f));
    }
}

// ---------------- scatter edges into packed CSR with fused edge weight --------
__global__ void scatter_edges_kernel(const int* __restrict__ src,
                                     const int* __restrict__ dst) {
    int e = blockIdx.x * blockDim.x + threadIdx.x;
    if (e < N_EDGES) {
        int s = src[e];
        int d = dst[e];
        int pos = atomicAdd(&g_cursor[d], 1);
        float nd = rsqrtf(fmaxf((float)g_deg_in[d], 1.0f));
        float w  = g_norm_src[s] * nd;
        g_csr[pos] = make_int2(s, __float_as_int(w));
    }
}

// ---------------- SpMM (CSR gather): one warp per dst node ----------------
__global__ __launch_bounds__(256)
void spmm_csr_kernel(const float* __restrict__ feat, int in_sel) {
    int node = blockIdx.x * (blockDim.x >> 5) + (threadIdx.x >> 5);
    if (node >= N_NODES) return;
    int lane = threadIdx.x & 31;

    const float* __restrict__ h = (in_sel < 0) ? feat : g_h[in_sel];
    const int2* __restrict__ csr = g_csr;

    int beg = g_row_ptr[node];
    int end = g_row_ptr[node + 1];

    float4 s0 = make_float4(0.f, 0.f, 0.f, 0.f);
    float4 s1 = make_float4(0.f, 0.f, 0.f, 0.f);
    float4 s2 = make_float4(0.f, 0.f, 0.f, 0.f);
    float4 s3 = make_float4(0.f, 0.f, 0.f, 0.f);

    int i = beg;
    for (; i + 3 < end; i += 4) {
        int2 e0 = csr[i];
        int2 e1 = csr[i + 1];
        int2 e2 = csr[i + 2];
        int2 e3 = csr[i + 3];
        float4 v0 = ((const float4*)(h + (size_t)e0.x * DIM))[lane];
        float4 v1 = ((const float4*)(h + (size_t)e1.x * DIM))[lane];
        float4 v2 = ((const float4*)(h + (size_t)e2.x * DIM))[lane];
        float4 v3 = ((const float4*)(h + (size_t)e3.x * DIM))[lane];
        float w0 = __int_as_float(e0.y);
        float w1 = __int_as_float(e1.y);
        float w2 = __int_as_float(e2.y);
        float w3 = __int_as_float(e3.y);
        s0.x += v0.x * w0; s0.y += v0.y * w0; s0.z += v0.z * w0; s0.w += v0.w * w0;
        s1.x += v1.x * w1; s1.y += v1.y * w1; s1.z += v1.z * w1; s1.w += v1.w * w1;
        s2.x += v2.x * w2; s2.y += v2.y * w2; s2.z += v2.z * w2; s2.w += v2.w * w2;
        s3.x += v3.x * w3; s3.y += v3.y * w3; s3.z += v3.z * w3; s3.w += v3.w * w3;
    }
    for (; i < end; i++) {
        int2 e0 = csr[i];
        float w0 = __int_as_float(e0.y);
        float4 v0 = ((const float4*)(h + (size_t)e0.x * DIM))[lane];
        s0.x += v0.x * w0; s0.y += v0.y * w0; s0.z += v0.z * w0; s0.w += v0.w * w0;
    }

    float4 o;
    o.x = (s0.x + s1.x) + (s2.x + s3.x);
    o.y = (s0.y + s1.y) + (s2.y + s3.y);
    o.z = (s0.z + s1.z) + (s2.z + s3.z);
    o.w = (s0.w + s1.w) + (s2.w + s3.w);
    ((float4*)(g_agg + (size_t)node * DIM))[lane] = o;
}

// ---------------- tensor-core GEMM: out = relu(agg @ W + b) ----------------
// 3xTF32 (a_hi*b_lo + a_lo*b_hi + a_hi*b_hi) for ~fp32 precision.
// Tile: BM=64, BN=128. 128 threads = 4 warps (2 M x 2 N), warp tile 32x64.
// K processed in chunks of 32 staged in smem; frags via conflict-free LDS.
__global__ __launch_bounds__(128, 4)
void gemm_tf32_kernel(const float* __restrict__ bias_p,
                      float* __restrict__ ext_out,
                      int layer, int out_sel) {
    __shared__ float As [64 * 36];    // 64 rows x 32 k (+4 pad)
    __shared__ float Bsh[32 * 136];   // 32 k x 128 n (+8 pad), W hi
    __shared__ float Bsl[32 * 136];   // W lo

    float* __restrict__ out = (out_sel < 0) ? ext_out : g_h[out_sel];
    const float* __restrict__ Whi = g_Whi + (size_t)layer * DIM * DIM;
    const float* __restrict__ Wlo = g_Wlo + (size_t)layer * DIM * DIM;

    const int tid  = threadIdx.x;
    const int lane = tid & 31;
    const int wrp  = tid >> 5;
    const int wm   = wrp & 1;       // warp's M half (32 rows)
    const int wn   = wrp >> 1;      // warp's N half (64 cols)
    const int gid  = lane >> 2;     // groupID (0..7)
    const int tg   = lane & 3;      // thread-in-group (0..3)
    const int rowBase = blockIdx.x * 64;

    float C[2][8][4];
    #pragma unroll
    for (int mt = 0; mt < 2; mt++)
        #pragma unroll
        for (int nt = 0; nt < 8; nt++)
            #pragma unroll
            for (int q = 0; q < 4; q++) C[mt][nt][q] = 0.0f;

    for (int kc = 0; kc < DIM; kc += 32) {
        if (kc) __syncthreads();   // protect smem reuse

        // stage A chunk: 64 rows x 32 k  (512 float4, 4 per thread)
        #pragma unroll
        for (int it = 0; it < 4; it++) {
            int f  = tid + it * 128;
            int r  = f >> 3;
            int cc = (f & 7) * 4;
            int grow = rowBase + r;
            float4 v = make_float4(0.f, 0.f, 0.f, 0.f);
            if (grow < N_NODES)
                v = *(const float4*)&g_agg[(size_t)grow * DIM + kc + cc];
            *(float4*)&As[r * 36 + cc] = v;
        }
        // stage W chunk hi/lo: 32 k x 128 n (1024 float4 each, 8 per thread)
        #pragma unroll
        for (int it = 0; it < 8; it++) {
            int f  = tid + it * 128;
            int kk = f >> 5;
            int nn = (f & 31) * 4;
            *(float4*)&Bsh[kk * 136 + nn] =
                *(const float4*)&Whi[(size_t)(kc + kk) * DIM + nn];
            *(float4*)&Bsl[kk * 136 + nn] =
                *(const float4*)&Wlo[(size_t)(kc + kk) * DIM + nn];
        }
        __syncthreads();

        #pragma unroll
        for (int k8 = 0; k8 < 4; k8++) {
            // A fragments for this warp's 2 m16 tiles, split hi/lo
            uint32_t ah[2][4], al[2][4];
            #pragma unroll
            for (int mt = 0; mt < 2; mt++) {
                int r0 = wm * 32 + mt * 16 + gid;
                int c0 = k8 * 8 + tg;
                float x0 = As[r0 * 36 + c0];
                float x1 = As[(r0 + 8) * 36 + c0];
                float x2 = As[r0 * 36 + c0 + 4];
                float x3 = As[(r0 + 8) * 36 + c0 + 4];
                split_tf32(x0, ah[mt][0], al[mt][0]);
                split_tf32(x1, ah[mt][1], al[mt][1]);
                split_tf32(x2, ah[mt][2], al[mt][2]);
                split_tf32(x3, ah[mt][3], al[mt][3]);
            }
            // loop n8 tiles: load B frags (hi+lo precomputed), 3x mma
            #pragma unroll
            for (int nt = 0; nt < 8; nt++) {
                int n = wn * 64 + nt * 8 + gid;
                int k = k8 * 8 + tg;
                uint32_t bh0 = __float_as_uint(Bsh[k * 136 + n]);
                uint32_t bh1 = __float_as_uint(Bsh[(k + 4) * 136 + n]);
                uint32_t bl0 = __float_as_uint(Bsl[k * 136 + n]);
                uint32_t bl1 = __float_as_uint(Bsl[(k + 4) * 136 + n]);
                #pragma unroll
                for (int mt = 0; mt < 2; mt++) {
                    mma_tf32(C[mt][nt], ah[mt], bl0, bl1);   // hi * lo
                    mma_tf32(C[mt][nt], al[mt], bh0, bh1);   // lo * hi
                    mma_tf32(C[mt][nt], ah[mt], bh0, bh1);   // hi * hi
                }
            }
        }
    }

    // epilogue: bias + relu, float2 stores
    #pragma unroll
    for (int nt = 0; nt < 8; nt++) {
        int col = wn * 64 + nt * 8 + 2 * tg;
        float b0 = bias_p[col];
        float b1 = bias_p[col + 1];
        #pragma unroll
        for (int mt = 0; mt < 2; mt++) {
            int row = rowBase + wm * 32 + mt * 16 + gid;
            if (row < N_NODES) {
                float2 o;
                o.x = fmaxf(C[mt][nt][0] + b0, 0.f);
                o.y = fmaxf(C[mt][nt][1] + b1, 0.f);
                *(float2*)&out[(size_t)row * DIM + col] = o;
            }
            if (row + 8 < N_NODES) {
                float2 o;
                o.x = fmaxf(C[mt][nt][2] + b0, 0.f);
                o.y = fmaxf(C[mt][nt][3] + b1, 0.f);
                *(float2*)&out[(size_t)(row + 8) * DIM + col] = o;
            }
        }
    }
}

// ---------------- launch ----------------
extern "C" void kernel_launch(void* const* d_in, const int* in_sizes, int n_in,
                              void* d_out, int out_size) {
    const float* feat = (const float*)d_in[0];   // [N, D]
    const int*   src  = (const int*)d_in[1];     // [E]
    const int*   dst  = (const int*)d_in[2];     // [E]
    const float* W    = (const float*)d_in[3];   // [L, D, D]
    const float* b    = (const float*)d_in[4];   // [L, D]
    float* out = (float*)d_out;                  // [N, D]

    (void)in_sizes; (void)n_in; (void)out_size;

    // ---- one-time CSR build + W split (per launch, graph-capturable) ----
    zero_deg_kernel<<<(N_NODES + 255) / 256, 256>>>();
    count_deg_kernel<<<(N_EDGES + 255) / 256, 256>>>(src, dst);
    scan_partial_kernel<<<SCAN_BLOCKS, SCAN_CHUNK>>>();
    scan_offsets_kernel<<<1, 256>>>();
    scan_write_kernel<<<SCAN_BLOCKS, SCAN_CHUNK>>>();
    scatter_edges_kernel<<<(N_EDGES + 255) / 256, 256>>>(src, dst);
    split_w_kernel<<<(LAYERS * DIM * DIM + 255) / 256, 256>>>(W);

    const int warps_per_block = 256 / 32;
    const int spmm_blocks = (N_NODES + warps_per_block - 1) / warps_per_block;
    const int gemm_blocks = (N_NODES + 63) / 64;   // 782

    for (int l = 0; l < LAYERS; l++) {
        int in_sel  = (l == 0) ? -1 : ((l - 1) & 1);
        int out_sel = (l == LAYERS - 1) ? -1 : (l & 1);

        spmm_csr_kernel<<<spmm_blocks, 256>>>(feat, in_sel);
        gemm_tf32_kernel<<<gemm_blocks, 128>>>(
            b + (size_t)l * DIM, out, l, out_sel);
    }
}